// round 8
// baseline (speedup 1.0000x reference)
#include <cuda_runtime.h>
#include <cuda_bf16.h>

// Problem: softmask [B=16, K=64, H=240, W=320] fp32.
// out = sqrt( sum over 1024 slices of unbiased variance over H*W=76800 elems )
//
// R8 experiment: explicit 8-deep load batching. All 8 LDG.E.128 of a batch
// are issued before any consumption, doubling per-thread outstanding loads
// vs the compiler's ~5-deep schedule (regs 29 -> ~50; occupancy proven
// irrelevant across 81-97%). Tests whether the 6.2 TB/s plateau is a hard
// DRAM ceiling or a latency/queue limit.
// Tail: fixed-point u64 atomicAdd (bit-deterministic), last CTA finalizes
// sqrt + resets (graph-replay safe).

#define HW        76800            // 240*320
#define HW4       (HW / 4)         // 19200 float4 per slice (75 per thread)
#define NSLICES   1024             // 16*64
#define NTHREADS  256
#define BATCH     8                // 75 = 9*8 + 3
#define NBATCH    9
#define NREM      3
#define FP_SCALE  1099511627776.0  // 2^40

__device__ unsigned long long g_acc   = 0ull;
__device__ unsigned int       g_count = 0;

__global__ __launch_bounds__(NTHREADS)
void loss_concentration_fused(const float4* __restrict__ in,
                              float* __restrict__ out) {
    const int s = blockIdx.x;
    const float4* __restrict__ p = in + (size_t)s * HW4 + threadIdx.x;

    float sum0 = 0.f, sq0 = 0.f;     // two independent chains
    float sum1 = 0.f, sq1 = 0.f;

    // 9 batches of 8 front-issued LDG.E.128 (stride NTHREADS between loads)
    #pragma unroll 1
    for (int b = 0; b < NBATCH; b++) {
        float4 v[BATCH];
        const float4* q = p + (size_t)b * (BATCH * NTHREADS);
        #pragma unroll
        for (int j = 0; j < BATCH; j++)
            v[j] = __ldcs(&q[(size_t)j * NTHREADS]);   // all issued first
        #pragma unroll
        for (int j = 0; j < BATCH; j++) {
            sum0 += v[j].x + v[j].y;
            sum1 += v[j].z + v[j].w;
            sq0  += v[j].x * v[j].x + v[j].y * v[j].y;
            sq1  += v[j].z * v[j].z + v[j].w * v[j].w;
        }
    }
    // remainder: 3 loads
    {
        float4 v[NREM];
        const float4* q = p + (size_t)(NBATCH * BATCH) * NTHREADS;
        #pragma unroll
        for (int j = 0; j < NREM; j++)
            v[j] = __ldcs(&q[(size_t)j * NTHREADS]);
        #pragma unroll
        for (int j = 0; j < NREM; j++) {
            sum0 += v[j].x + v[j].y;
            sum1 += v[j].z + v[j].w;
            sq0  += v[j].x * v[j].x + v[j].y * v[j].y;
            sq1  += v[j].z * v[j].z + v[j].w * v[j].w;
        }
    }
    float sum = sum0 + sum1;
    float sq  = sq0  + sq1;

    // warp reduce
    #pragma unroll
    for (int off = 16; off > 0; off >>= 1) {
        sum += __shfl_xor_sync(0xffffffffu, sum, off);
        sq  += __shfl_xor_sync(0xffffffffu, sq,  off);
    }

    __shared__ float s_sum[NTHREADS / 32];
    __shared__ float s_sq [NTHREADS / 32];
    const int lane = threadIdx.x & 31;
    const int wid  = threadIdx.x >> 5;
    if (lane == 0) { s_sum[wid] = sum; s_sq[wid] = sq; }
    __syncthreads();

    if (threadIdx.x == 0) {
        float tsum = 0.f, tsq = 0.f;
        #pragma unroll
        for (int w = 0; w < NTHREADS / 32; w++) { tsum += s_sum[w]; tsq += s_sq[w]; }
        // unbiased: (sumsq - sum^2/n) / (n-1)
        float var = (tsq - tsum * tsum * (1.0f / (float)HW))
                    * (1.0f / (float)(HW - 1));
        if (var < 0.f) var = 0.f;                // numerical guard
        // fixed-point contribution: deterministic under any atomic order
        unsigned long long q =
            (unsigned long long)(__double2ll_rn((double)var * FP_SCALE));
        atomicAdd(&g_acc, q);
        __threadfence();                         // acc visible before count
        unsigned old = atomicAdd(&g_count, 1u);
        if (old == NSLICES - 1) {
            unsigned long long total = atomicAdd(&g_acc, 0ull);  // coherent read
            out[0] = sqrtf((float)((double)total * (1.0 / FP_SCALE)));
            g_acc   = 0ull;                      // reset for next graph replay
            g_count = 0;
        }
    }
}

extern "C" void kernel_launch(void* const* d_in, const int* in_sizes, int n_in,
                              void* d_out, int out_size) {
    const float4* in = (const float4*)d_in[0];
    float* out = (float*)d_out;
    loss_concentration_fused<<<NSLICES, NTHREADS>>>(in, out);
}